// round 8
// baseline (speedup 1.0000x reference)
#include <cuda_runtime.h>
#include <math_constants.h>

#define B    32
#define T    336
#define C    7
#define NSH  5
#define NG   4
#define NF   140            // 4 groups * 5 * 7
#define OUTC 10
#define NWORKBLK (B * C * NSH)      // 1120 worker blocks (bc, nn); 4 warps = 4 g's
#define NWARPS   (B * C * NG * NSH) // 4480 warp work items
#define NHEAD    21                 // 20 dot blocks + 1 loss block

// offsets in d_out (floats): out[320] | dists[4480] | probs[4480] | loss[1]
#define OFF_OUT   0
#define OFF_DIST  320
#define OFF_PROB  (320 + B*NF)
#define OFF_LOSS  (320 + 2*B*NF)

#define SXN   464          // padded x length (float4 multiple, covers all reads)
#define BIGV  1.0e30f      // pad value: invalid windows accumulate huge sums

__device__ int g_ctr  = 0;   // worker warps completed
__device__ int g_ctr2 = 0;   // head blocks completed

typedef unsigned long long u64;

__device__ __forceinline__ u64 f2add(u64 a, u64 b) {
    u64 d;
    asm("add.rn.f32x2 %0, %1, %2;" : "=l"(d) : "l"(a), "l"(b));
    return d;
}
__device__ __forceinline__ u64 f2abs(u64 a) {
    return a & 0x7fffffff7fffffffULL;       // 2x LOP3 (alu pipe)
}
__device__ __forceinline__ float u64lo(u64 a) { return __uint_as_float((unsigned)a); }
__device__ __forceinline__ float u64hi(u64 a) { return __uint_as_float((unsigned)(a >> 32)); }

// ---------------------------------------------------------------------------
// Packed sliding min: lane ll owns window quads at j = 4*ll + 128*m.
// Even-l pairs come from sx (as ulonglong2 float4 chain), odd-l pairs from the
// +1-shifted copy sxs — every (x[t],x[t+1]) pair is a natural aligned u64.
// acc A covers windows (j, j+1), acc Bq covers (j+2, j+3), both packed f32x2.
// w2n[l] = (-w[l], -w[l]) so add.rn.f32x2 computes the subtraction.
// ---------------------------------------------------------------------------
template<int L, int M>
__device__ __forceinline__ float warp_sliding_pk(const ulonglong2* __restrict__ sx4,
                                                 const ulonglong2* __restrict__ sxs4,
                                                 const u64* __restrict__ w2n,
                                                 int ll) {
    float best = CUDART_INF_F;
    #pragma unroll
    for (int m = 0; m < M; m++) {
        const int v = ll + 32 * m;             // float4 index; j = 4*v
        ulonglong2 E0 = sx4[v],  E1 = sx4[v + 1];
        ulonglong2 O0 = sxs4[v], O1 = sxs4[v + 1];
        u64 A = 0ull, Bq = 0ull;
        int vv = v + 2;

        #pragma unroll 4
        for (int l = 0; l < (L & ~3); l += 4) {
            u64 w;
            w = w2n[l];                         // broadcast LDS.64
            A  = f2add(A,  f2abs(f2add(E0.x, w)));
            Bq = f2add(Bq, f2abs(f2add(E0.y, w)));
            w = w2n[l + 1];
            A  = f2add(A,  f2abs(f2add(O0.x, w)));
            Bq = f2add(Bq, f2abs(f2add(O0.y, w)));
            w = w2n[l + 2];
            A  = f2add(A,  f2abs(f2add(E0.y, w)));
            Bq = f2add(Bq, f2abs(f2add(E1.x, w)));
            w = w2n[l + 3];
            A  = f2add(A,  f2abs(f2add(O0.y, w)));
            Bq = f2add(Bq, f2abs(f2add(O1.x, w)));
            E0 = E1; E1 = sx4[vv];              // conflict-free LDS.128
            O0 = O1; O1 = sxs4[vv];
            vv++;
        }
        if ((L & 3) >= 1) {                     // remainder (even step)
            u64 w = w2n[L & ~3];
            A  = f2add(A,  f2abs(f2add(E0.x, w)));
            Bq = f2add(Bq, f2abs(f2add(E0.y, w)));
        }
        if ((L & 3) >= 2) {                     // remainder (odd step)
            u64 w = w2n[(L & ~3) + 1];
            A  = f2add(A,  f2abs(f2add(O0.x, w)));
            Bq = f2add(Bq, f2abs(f2add(O0.y, w)));
        }
        best = fminf(best, fminf(fminf(u64lo(A), u64hi(A)),
                                 fminf(u64lo(Bq), u64hi(Bq))));
    }
    #pragma unroll
    for (int o = 16; o > 0; o >>= 1)
        best = fminf(best, __shfl_xor_sync(0xffffffffu, best, o));
    return best * (1.0f / (float)L);
}

// sw2n row offsets (u64 units): g0@0(34) g1@40(68) g2@112(101) g3@216(168)
#define SW2N_TOT 384

// ---------------------------------------------------------------------------
// Single launch. grid.x = 1120 workers + 21 head blocks, 128 threads.
// ---------------------------------------------------------------------------
__global__ __launch_bounds__(128, 6) void fused_kernel(
        const float* __restrict__ x,
        const float* __restrict__ w0,
        const float* __restrict__ w1,
        const float* __restrict__ w2,
        const float* __restrict__ w3,
        const float* __restrict__ Wout,
        float* __restrict__ d_out) {
    const int bid = blockIdx.x;
    const int tid = threadIdx.x;          // 128

    if (bid < NWORKBLK) {
        // ================= WORKER =================
        const int nn = bid % NSH;
        const int bc = bid / NSH;
        const int b  = bc / C;
        const int ch = bc % C;
        const int wp = tid >> 5;             // warp 0..3
        const int ll = tid & 31;
        const int g  = (wp + bid) & 3;       // rotate g across blocks/SMSPs

        __shared__ __align__(16) float sx[SXN];
        __shared__ __align__(16) float sxs[SXN];   // sxs[i] = sx[i+1]
        __shared__ __align__(16) u64   sw2n[SW2N_TOT];
        __shared__ float red[8];

        // ---- normalization: one pass sum + sumsq over the (b,ch) row ----
        const float* xrow = x + (size_t)b * T * C + ch;   // stride C over t
        float vals[3];
        float s = 0.f, ss = 0.f;
        #pragma unroll
        for (int i = 0; i < 3; i++) {
            int t = tid + i * 128;
            float v = (t < T) ? xrow[(size_t)t * C] : 0.f;
            vals[i] = v;
            s += v;
            ss += v * v;
        }
        #pragma unroll
        for (int o = 16; o > 0; o >>= 1) {
            s  += __shfl_xor_sync(0xffffffffu, s, o);
            ss += __shfl_xor_sync(0xffffffffu, ss, o);
        }
        if (ll == 0) { red[wp] = s; red[4 + wp] = ss; }

        // ---- each warp builds its negated, duplicated shapelet row ----
        int L, goff;
        const float* wg;
        switch (g) {
            case 0:  L = 34;  goff = 0;   wg = w0; break;
            case 1:  L = 68;  goff = 40;  wg = w1; break;
            case 2:  L = 101; goff = 112; wg = w2; break;
            default: L = 168; goff = 216; wg = w3; break;
        }
        const float* wrow = wg + (size_t)(nn * C + ch) * L;
        for (int i = ll; i < L; i += 32) {
            unsigned nb = __float_as_uint(-wrow[i]);
            sw2n[goff + i] = ((u64)nb << 32) | nb;
        }

        __syncthreads();
        const float stot  = red[0] + red[1] + red[2] + red[3];
        const float sstot = red[4] + red[5] + red[6] + red[7];
        const float mu  = stot * (1.0f / (float)T);
        const float var = (sstot - (float)T * mu * mu) * (1.0f / (float)(T - 1));
        const float inv = 1.0f / (sqrtf(fmaxf(var, 0.f)) + 1e-8f);

        #pragma unroll
        for (int i = 0; i < 3; i++) {
            int t = tid + i * 128;
            if (t < T) {
                float v = (vals[i] - mu) * inv;
                sx[t] = v;
                if (t > 0) sxs[t - 1] = v;
            }
        }
        // pads: invalid windows accumulate BIGV -> excluded from min
        for (int i = T + tid; i < SXN; i += 128)      sx[i]  = BIGV;
        for (int i = T - 1 + tid; i < SXN; i += 128)  sxs[i] = BIGV;
        __syncthreads();

        const ulonglong2* sx4  = reinterpret_cast<const ulonglong2*>(sx);
        const ulonglong2* sxs4 = reinterpret_cast<const ulonglong2*>(sxs);

        float dmin;
        switch (g) {
            case 0:  dmin = warp_sliding_pk<34, 3>(sx4, sxs4, sw2n + 0,   ll); break;
            case 1:  dmin = warp_sliding_pk<68, 3>(sx4, sxs4, sw2n + 40,  ll); break;
            case 2:  dmin = warp_sliding_pk<101,2>(sx4, sxs4, sw2n + 112, ll); break;
            default: dmin = warp_sliding_pk<168,2>(sx4, sxs4, sw2n + 216, ll); break;
        }

        if (ll == 0) {
            const int idx = b * NF + g * (NSH * C) + nn * C + ch;
            d_out[OFF_DIST + idx] = dmin;
            d_out[OFF_PROB + idx] = expf(-dmin * dmin);   // EPS_GATE = 1
            __threadfence();
            atomicAdd(&g_ctr, 1);        // publish this warp's result
        }
    } else {
        // ================= HEAD =================
        const int h = bid - NWORKBLK;    // 0..20

        if (tid == 0) {
            while (atomicAdd(&g_ctr, 0) < NWARPS) __nanosleep(64);
        }
        __syncthreads();
        __threadfence();                  // acquire published probs

        if (h < 20) {
            // 16 dots per block; warp wp does 4 dots
            const int wp = tid >> 5;
            const int ln = tid & 31;
            const float* probs = d_out + OFF_PROB;
            #pragma unroll
            for (int d = 0; d < 4; d++) {
                const int dot = h * 16 + wp * 4 + d;     // < 320
                const int b = dot / OUTC;
                const int o = dot % OUTC;
                const float* p  = probs + b * NF;
                const float* wv = Wout + o * NF;
                float v = 0.f;
                #pragma unroll
                for (int f = ln; f < NF; f += 32) v += p[f] * wv[f];
                #pragma unroll
                for (int off = 16; off > 0; off >>= 1)
                    v += __shfl_xor_sync(0xffffffffu, v, off);
                if (ln == 0) d_out[OFF_OUT + dot] = v;
            }
        } else {
            // loss = 0.1 * mean|Wout|
            __shared__ float sred[4];
            float v = 0.f;
            #pragma unroll
            for (int i = tid; i < OUTC * NF; i += 128) v += fabsf(Wout[i]);
            #pragma unroll
            for (int off = 16; off > 0; off >>= 1)
                v += __shfl_xor_sync(0xffffffffu, v, off);
            if ((tid & 31) == 0) sred[tid >> 5] = v;
            __syncthreads();
            if (tid == 0) {
                float tot = sred[0] + sred[1] + sred[2] + sred[3];
                d_out[OFF_LOSS] = 0.1f * tot / (float)(OUTC * NF);
            }
        }

        __syncthreads();
        if (tid == 0) {
            int v = atomicAdd(&g_ctr2, 1);
            if (v == NHEAD - 1) {
                // last head block resets counters for the next graph replay
                atomicExch(&g_ctr, 0);
                atomicExch(&g_ctr2, 0);
            }
        }
    }
}

// ---------------------------------------------------------------------------
extern "C" void kernel_launch(void* const* d_in, const int* in_sizes, int n_in,
                              void* d_out, int out_size) {
    const float* x    = (const float*)d_in[0];
    const float* w0   = (const float*)d_in[1];
    const float* w1   = (const float*)d_in[2];
    const float* w2   = (const float*)d_in[3];
    const float* w3   = (const float*)d_in[4];
    const float* Wout = (const float*)d_in[5];
    float* out = (float*)d_out;

    fused_kernel<<<NWORKBLK + NHEAD, 128>>>(x, w0, w1, w2, w3, Wout, out);
}

// round 9
// speedup vs baseline: 1.4184x; 1.4184x over previous
#include <cuda_runtime.h>
#include <math_constants.h>

#define B    32
#define T    336
#define C    7
#define NSH  5
#define NG   4
#define NF   140            // 4 groups * 5 * 7
#define OUTC 10
#define NWORKBLK (B * NSH * NG)    // 640 worker blocks: one per (b, nn, g), 7 ch pooled
#define NHEAD    21                // 20 dot blocks + 1 loss block

// offsets in d_out (floats): out[320] | dists[4480] | probs[4480] | loss[1]
#define OFF_OUT   0
#define OFF_DIST  320
#define OFF_PROB  (320 + B*NF)
#define OFF_LOSS  (320 + 2*B*NF)

#define XROW4 87                   // x row stride in float4 (87 mod 8 = 7 -> conflict-free across ch)
#define XROWF (XROW4 * 4)          // 348 floats
#define WMAX4 (7 * 45)             // max w smem float4 (g3: S4=45)

__device__ int g_ctr  = 0;   // worker blocks completed
__device__ int g_ctr2 = 0;   // head blocks completed

// ---------------------------------------------------------------------------
// Load 7 channel rows of shapelet nn into smem, row stride S4 float4 (odd ->
// the 7 ch rows start in distinct 16B bank groups).
// ---------------------------------------------------------------------------
template<int L>
__device__ __forceinline__ void load_w(float* __restrict__ swv,
                                       const float* __restrict__ wg,
                                       int nn, int tid) {
    constexpr int S4 = ((L + 3) / 4 + 2) | 1;
    const float* src = wg + (size_t)nn * 7 * L;    // 7 contiguous ch rows
    for (int i = tid; i < 7 * L; i += 128) {
        int ch = i / L, l = i - ch * L;
        swv[ch * S4 * 4 + l] = src[i];
    }
}

// ---------------------------------------------------------------------------
// Pooled-channel quad sweep. Quads indexed q = ch*QC + jq over all 7 channels;
// warp wp takes passes p = wp, wp+4, ... Each lane: one quad (4 windows) per
// pass, rolling float4 double-buffer, per-4-steps: 1 LDS.128 x + 1 LDS.128 w
// + 32 FADD. Invalid windows start at +inf; result merged via smem atomicMin.
// ---------------------------------------------------------------------------
template<int L>
__device__ __forceinline__ void slide_group(const float* __restrict__ sxAll,
                                            const float* __restrict__ swAll,
                                            unsigned* __restrict__ smin,
                                            int wp, int ll) {
    constexpr int TW  = T - L + 1;
    constexpr int QC  = (TW + 3) / 4;      // quads per channel
    constexpr int Q   = 7 * QC;            // total quads
    constexpr int P   = (Q + 31) / 32;     // warp passes
    constexpr int LV  = L / 4;
    constexpr int REM = L % 4;
    constexpr int S4  = ((L + 3) / 4 + 2) | 1;

    const float4* x4 = reinterpret_cast<const float4*>(sxAll);
    const float4* w4 = reinterpret_cast<const float4*>(swAll);

    for (int p = wp; p < P; p += 4) {
        int q = p * 32 + ll;
        if (q >= Q) q = Q - 1;              // duplicate work, min-safe
        const int ch = q / QC;
        const int jq = q - ch * QC;
        const int j  = 4 * jq;              // j <= TW-1, 16B aligned

        const float4* xr = x4 + ch * XROW4 + jq;
        const float4* wr = w4 + ch * S4;

        float4 lo = xr[0];
        float4 hi = xr[1];
        float a0 = 0.f;
        float a1 = (j + 1 < TW) ? 0.f : CUDART_INF_F;
        float a2 = (j + 2 < TW) ? 0.f : CUDART_INF_F;
        float a3 = (j + 3 < TW) ? 0.f : CUDART_INF_F;

        #pragma unroll 2
        for (int lv = 0; lv < LV; lv++) {
            const float4 wv = wr[lv];                  // conflict-free LDS.128
            const float x0 = lo.x, x1 = lo.y, x2 = lo.z, x3 = lo.w;
            const float x4v = hi.x, x5 = hi.y, x6 = hi.z;

            a0 += fabsf(x0 - wv.x); a1 += fabsf(x1 - wv.x);
            a2 += fabsf(x2 - wv.x); a3 += fabsf(x3 - wv.x);

            a0 += fabsf(x1 - wv.y); a1 += fabsf(x2 - wv.y);
            a2 += fabsf(x3 - wv.y); a3 += fabsf(x4v - wv.y);

            a0 += fabsf(x2 - wv.z); a1 += fabsf(x3 - wv.z);
            a2 += fabsf(x4v - wv.z); a3 += fabsf(x5 - wv.z);

            a0 += fabsf(x3 - wv.w); a1 += fabsf(x4v - wv.w);
            a2 += fabsf(x5 - wv.w); a3 += fabsf(x6 - wv.w);

            lo = hi;
            hi = xr[lv + 2];                           // conflict-free LDS.128
        }
        if (REM > 0) {
            const float xs[7] = { lo.x, lo.y, lo.z, lo.w, hi.x, hi.y, hi.z };
            const float* wsc = swAll + ch * S4 * 4;
            #pragma unroll
            for (int r = 0; r < REM; r++) {
                const float wv = wsc[4 * LV + r];
                a0 += fabsf(xs[r]     - wv);
                a1 += fabsf(xs[r + 1] - wv);
                a2 += fabsf(xs[r + 2] - wv);
                a3 += fabsf(xs[r + 3] - wv);
            }
        }
        const float mn = fminf(fminf(a0, a1), fminf(a2, a3));
        atomicMin(&smin[ch], __float_as_uint(mn));     // d >= 0: bits monotone
    }
}

// ---------------------------------------------------------------------------
// Single launch. grid.x = 640 workers + 21 head blocks, 128 threads.
// ---------------------------------------------------------------------------
__global__ __launch_bounds__(128, 8) void fused_kernel(
        const float* __restrict__ x,
        const float* __restrict__ w0,
        const float* __restrict__ w1,
        const float* __restrict__ w2,
        const float* __restrict__ w3,
        const float* __restrict__ Wout,
        float* __restrict__ d_out) {
    const int bid = blockIdx.x;
    const int tid = threadIdx.x;          // 128

    if (bid < NWORKBLK) {
        // ================= WORKER: one (b, nn, g), all 7 ch =================
        const int graw = bid & 3;
        const int rest = bid >> 2;
        const int nn   = rest % NSH;
        const int b    = rest / NSH;
        const int g    = (graw + b + nn) & 3;   // mix lengths across waves
        const int wp   = tid >> 5;
        const int ll   = tid & 31;

        __shared__ __align__(16) float sx[7 * XROWF];      // 9744 B
        __shared__ __align__(16) float swv[WMAX4 * 4];     // 5040 B
        __shared__ unsigned smin[7];
        __shared__ float smu[7], sinv[7];

        // ---- load this b's full row (2352 contiguous floats), transpose ----
        const float* xb = x + (size_t)b * T * C;
        for (int i = tid; i < T * C; i += 128) {
            int t = i / C, ch = i - t * C;
            sx[ch * XROWF + t] = xb[i];
        }
        if (tid < 7) smin[tid] = 0x7f800000u;   // +inf bits
        __syncthreads();

        // ---- per-channel stats (warp wp handles ch wp, wp+4) ----
        #pragma unroll
        for (int rep = 0; rep < 2; rep++) {
            const int ch = wp + 4 * rep;
            if (ch < 7) {
                float s = 0.f, ss = 0.f;
                for (int t = ll; t < T; t += 32) {
                    float v = sx[ch * XROWF + t];
                    s += v; ss += v * v;
                }
                #pragma unroll
                for (int o = 16; o > 0; o >>= 1) {
                    s  += __shfl_xor_sync(0xffffffffu, s, o);
                    ss += __shfl_xor_sync(0xffffffffu, ss, o);
                }
                if (ll == 0) {
                    const float mu  = s * (1.0f / (float)T);
                    const float var = (ss - (float)T * mu * mu) * (1.0f / (float)(T - 1));
                    smu[ch]  = mu;
                    sinv[ch] = 1.0f / (sqrtf(fmaxf(var, 0.f)) + 1e-8f);
                }
            }
        }
        __syncthreads();

        // ---- normalize in place + zero pads ----
        for (int i = tid; i < 7 * XROWF; i += 128) {
            const int ch = i / XROWF;
            const int t  = i - ch * XROWF;
            sx[i] = (t < T) ? (sx[i] - smu[ch]) * sinv[ch] : 0.f;
        }

        // ---- load w rows, then sweep ----
        switch (g) {
            case 0:  load_w<34>(swv, w0, nn, tid);  __syncthreads();
                     slide_group<34>(sx, swv, smin, wp, ll);  break;
            case 1:  load_w<68>(swv, w1, nn, tid);  __syncthreads();
                     slide_group<68>(sx, swv, smin, wp, ll);  break;
            case 2:  load_w<101>(swv, w2, nn, tid); __syncthreads();
                     slide_group<101>(sx, swv, smin, wp, ll); break;
            default: load_w<168>(swv, w3, nn, tid); __syncthreads();
                     slide_group<168>(sx, swv, smin, wp, ll); break;
        }
        __syncthreads();

        if (tid == 0) {
            const float invL = (g == 0) ? (1.f/34.f) : (g == 1) ? (1.f/68.f)
                             : (g == 2) ? (1.f/101.f) : (1.f/168.f);
            #pragma unroll
            for (int ch = 0; ch < 7; ch++) {
                const float dmin = __uint_as_float(smin[ch]) * invL;
                const int idx = b * NF + g * (NSH * C) + nn * C + ch;
                d_out[OFF_DIST + idx] = dmin;
                d_out[OFF_PROB + idx] = expf(-dmin * dmin);   // EPS_GATE = 1
            }
            __threadfence();
            atomicAdd(&g_ctr, 1);
        }
    } else {
        // ================= HEAD =================
        const int h = bid - NWORKBLK;    // 0..20

        if (tid == 0) {
            while (atomicAdd(&g_ctr, 0) < NWORKBLK) __nanosleep(64);
        }
        __syncthreads();
        __threadfence();                  // acquire published probs

        if (h < 20) {
            // 16 dots per block; warp wp does 4 dots
            const int wp = tid >> 5;
            const int ln = tid & 31;
            const float* probs = d_out + OFF_PROB;
            #pragma unroll
            for (int d = 0; d < 4; d++) {
                const int dot = h * 16 + wp * 4 + d;     // < 320
                const int bb = dot / OUTC;
                const int o  = dot % OUTC;
                const float* p  = probs + bb * NF;
                const float* wv = Wout + o * NF;
                float v = 0.f;
                #pragma unroll
                for (int f = ln; f < NF; f += 32) v += p[f] * wv[f];
                #pragma unroll
                for (int off = 16; off > 0; off >>= 1)
                    v += __shfl_xor_sync(0xffffffffu, v, off);
                if (ln == 0) d_out[OFF_OUT + dot] = v;
            }
        } else {
            // loss = 0.1 * mean|Wout|
            __shared__ float sred[4];
            float v = 0.f;
            #pragma unroll
            for (int i = tid; i < OUTC * NF; i += 128) v += fabsf(Wout[i]);
            #pragma unroll
            for (int off = 16; off > 0; off >>= 1)
                v += __shfl_xor_sync(0xffffffffu, v, off);
            if ((tid & 31) == 0) sred[tid >> 5] = v;
            __syncthreads();
            if (tid == 0) {
                float tot = sred[0] + sred[1] + sred[2] + sred[3];
                d_out[OFF_LOSS] = 0.1f * tot / (float)(OUTC * NF);
            }
        }

        __syncthreads();
        if (tid == 0) {
            int v = atomicAdd(&g_ctr2, 1);
            if (v == NHEAD - 1) {
                // last head block resets counters for the next graph replay
                atomicExch(&g_ctr, 0);
                atomicExch(&g_ctr2, 0);
            }
        }
    }
}

// ---------------------------------------------------------------------------
extern "C" void kernel_launch(void* const* d_in, const int* in_sizes, int n_in,
                              void* d_out, int out_size) {
    const float* x    = (const float*)d_in[0];
    const float* w0   = (const float*)d_in[1];
    const float* w1   = (const float*)d_in[2];
    const float* w2   = (const float*)d_in[3];
    const float* w3   = (const float*)d_in[4];
    const float* Wout = (const float*)d_in[5];
    float* out = (float*)d_out;

    fused_kernel<<<NWORKBLK + NHEAD, 128>>>(x, w0, w1, w2, w3, Wout, out);
}

// round 10
// speedup vs baseline: 1.6977x; 1.1969x over previous
#include <cuda_runtime.h>
#include <math_constants.h>

#define B    32
#define T    336
#define C    7
#define NSH  5
#define NG   4
#define NF   140            // 4 groups * 5 * 7
#define OUTC 10
#define NWORKBLK (B * C * NSH)      // 1120 worker blocks (bc, nn); 4 warps = 4 g's
#define NWARPS   (B * C * NG * NSH) // 4480 warp work items
#define NHEAD    21                 // 20 dot blocks + 1 loss block

// offsets in d_out (floats): out[320] | dists[4480] | probs[4480] | loss[1]
#define OFF_OUT   0
#define OFF_DIST  320
#define OFF_PROB  (320 + B*NF)
#define OFF_LOSS  (320 + 2*B*NF)

#define SXE_N 176          // even/odd split array length (T/2=168 + pad)

__device__ int g_ctr  = 0;   // worker warps completed
__device__ int g_ctr2 = 0;   // head blocks completed

// ---------------------------------------------------------------------------
// One warp computes min over all windows for one (bc, g, nn).
// Window-pair base bb = 2*beta, beta = min(ll + 32*m, BETAMAX).
// x stored as even/odd split (sxe[i]=x[2i], sxo[i]=x[2i+1]) so every rolling
// load is stride-1 across lanes -> conflict-free LDS. 1 LDS feeds 2 windows.
// Pairs whose second window is out of range start at +inf (excluded from min).
// ---------------------------------------------------------------------------
template<int L, int M>
__device__ __forceinline__ float warp_sliding_eo(const float* __restrict__ sxe,
                                                 const float* __restrict__ sxo,
                                                 const float* __restrict__ swg,
                                                 int ll) {
    constexpr int TW      = T - L + 1;
    constexpr int BETAMAX = ((TW - 1) & ~1) / 2;   // max even pair base / 2
    constexpr int H       = L / 2;

    int   beta[M];
    float a0[M], a1[M], E[M], O[M];
    #pragma unroll
    for (int m = 0; m < M; m++) {
        int bt = ll + 32 * m;
        if (bt > BETAMAX) bt = BETAMAX;            // duplicate work, min-safe
        beta[m] = bt;
        a0[m] = 0.f;
        a1[m] = (2 * bt + 1 < TW) ? 0.f : CUDART_INF_F;
        E[m]  = sxe[bt];                            // x[bb]
        O[m]  = sxo[bt];                            // x[bb+1]
    }

    #pragma unroll 2
    for (int h = 0; h < H; h++) {
        const float w0 = swg[2 * h];                // broadcast
        const float w1 = swg[2 * h + 1];            // broadcast
        #pragma unroll
        for (int m = 0; m < M; m++) {
            const float E1 = sxe[beta[m] + h + 1];  // stride-1, conflict-free
            // l = 2h   : a0 uses x[bb+2h]=E, a1 uses x[bb+2h+1]=O
            a0[m] += fabsf(E[m] - w0);
            a1[m] += fabsf(O[m] - w0);
            // l = 2h+1 : a0 uses x[bb+2h+1]=O, a1 uses x[bb+2h+2]=E1
            a0[m] += fabsf(O[m] - w1);
            a1[m] += fabsf(E1  - w1);
            E[m] = E1;
            O[m] = sxo[beta[m] + h + 1];            // stride-1, conflict-free
        }
    }
    if (L & 1) {                                    // final even step l = L-1
        const float w0 = swg[L - 1];
        #pragma unroll
        for (int m = 0; m < M; m++) {
            a0[m] += fabsf(E[m] - w0);
            a1[m] += fabsf(O[m] - w0);
        }
    }

    float mn = CUDART_INF_F;
    #pragma unroll
    for (int m = 0; m < M; m++) mn = fminf(mn, fminf(a0[m], a1[m]));
    #pragma unroll
    for (int o = 16; o > 0; o >>= 1)
        mn = fminf(mn, __shfl_xor_sync(0xffffffffu, mn, o));
    return mn * (1.0f / (float)L);
}

// sw row offsets: g0@0(len34) g1@36(68) g2@104(101) g3@208(168)
#define SW_TOT 376

// ---------------------------------------------------------------------------
// Single launch. grid.x = 1120 workers + 21 head blocks, 128 threads.
// ---------------------------------------------------------------------------
__global__ __launch_bounds__(128, 8) void fused_kernel(
        const float* __restrict__ x,
        const float* __restrict__ w0,
        const float* __restrict__ w1,
        const float* __restrict__ w2,
        const float* __restrict__ w3,
        const float* __restrict__ Wout,
        float* __restrict__ d_out) {
    const int bid = blockIdx.x;
    const int tid = threadIdx.x;          // 128

    if (bid < NWORKBLK) {
        // ================= WORKER =================
        const int nn = bid % NSH;
        const int bc = bid / NSH;
        const int b  = bc / C;
        const int ch = bc % C;
        const int wp = tid >> 5;             // warp 0..3
        const int ll = tid & 31;
        const int g  = (wp + bid) & 3;       // rotate g across blocks/SMSPs

        __shared__ __align__(16) float sxe[SXE_N];   // x[2i]
        __shared__ __align__(16) float sxo[SXE_N];   // x[2i+1]
        __shared__ __align__(16) float sw[SW_TOT];
        __shared__ float red[8];

        // ---- normalization: one pass sum + sumsq over the (b,ch) row ----
        const float* xrow = x + (size_t)b * T * C + ch;   // stride C over t
        float vals[3];
        float s = 0.f, ss = 0.f;
        #pragma unroll
        for (int i = 0; i < 3; i++) {
            int t = tid + i * 128;
            float v = (t < T) ? xrow[(size_t)t * C] : 0.f;
            vals[i] = v;
            s += v;
            ss += v * v;
        }
        #pragma unroll
        for (int o = 16; o > 0; o >>= 1) {
            s  += __shfl_xor_sync(0xffffffffu, s, o);
            ss += __shfl_xor_sync(0xffffffffu, ss, o);
        }
        if (ll == 0) { red[wp] = s; red[4 + wp] = ss; }

        // ---- each warp loads its own shapelet row meanwhile ----
        int L, goff;
        const float* wg;
        switch (g) {
            case 0:  L = 34;  goff = 0;   wg = w0; break;
            case 1:  L = 68;  goff = 36;  wg = w1; break;
            case 2:  L = 101; goff = 104; wg = w2; break;
            default: L = 168; goff = 208; wg = w3; break;
        }
        const float* wrow = wg + (size_t)(nn * C + ch) * L;
        for (int i = ll; i < L; i += 32) sw[goff + i] = wrow[i];

        __syncthreads();
        const float stot  = red[0] + red[1] + red[2] + red[3];
        const float sstot = red[4] + red[5] + red[6] + red[7];
        const float mu  = stot * (1.0f / (float)T);
        const float var = (sstot - (float)T * mu * mu) * (1.0f / (float)(T - 1));
        const float inv = 1.0f / (sqrtf(fmaxf(var, 0.f)) + 1e-8f);

        #pragma unroll
        for (int i = 0; i < 3; i++) {
            int t = tid + i * 128;
            if (t < T) {
                float v = (vals[i] - mu) * inv;
                if (t & 1) sxo[t >> 1] = v;
                else       sxe[t >> 1] = v;
            }
        }
        // zero pads beyond T/2 = 168 (only invalid +inf windows touch them)
        if (tid < SXE_N - 168) {
            sxe[168 + tid] = 0.f;
            sxo[168 + tid] = 0.f;
        }
        __syncthreads();

        // ---- per-warp sliding min (conflict-free even/odd) ----
        float dmin;
        switch (g) {
            case 0:  dmin = warp_sliding_eo<34, 5>(sxe, sxo, sw + 0,   ll); break;
            case 1:  dmin = warp_sliding_eo<68, 5>(sxe, sxo, sw + 36,  ll); break;
            case 2:  dmin = warp_sliding_eo<101,4>(sxe, sxo, sw + 104, ll); break;
            default: dmin = warp_sliding_eo<168,3>(sxe, sxo, sw + 208, ll); break;
        }

        if (ll == 0) {
            const int idx = b * NF + g * (NSH * C) + nn * C + ch;
            d_out[OFF_DIST + idx] = dmin;
            d_out[OFF_PROB + idx] = expf(-dmin * dmin);   // EPS_GATE = 1
            __threadfence();
            atomicAdd(&g_ctr, 1);        // publish this warp's result
        }
    } else {
        // ================= HEAD =================
        const int h = bid - NWORKBLK;    // 0..20

        if (tid == 0) {
            while (atomicAdd(&g_ctr, 0) < NWARPS) __nanosleep(64);
        }
        __syncthreads();
        __threadfence();                  // acquire published probs

        if (h < 20) {
            // 16 dots per block; warp wp does 4 dots
            const int wp = tid >> 5;
            const int ln = tid & 31;
            const float* probs = d_out + OFF_PROB;
            #pragma unroll
            for (int d = 0; d < 4; d++) {
                const int dot = h * 16 + wp * 4 + d;     // < 320
                const int bb = dot / OUTC;
                const int o  = dot % OUTC;
                const float* p  = probs + bb * NF;
                const float* wv = Wout + o * NF;
                float v = 0.f;
                #pragma unroll
                for (int f = ln; f < NF; f += 32) v += p[f] * wv[f];
                #pragma unroll
                for (int off = 16; off > 0; off >>= 1)
                    v += __shfl_xor_sync(0xffffffffu, v, off);
                if (ln == 0) d_out[OFF_OUT + dot] = v;
            }
        } else {
            // loss = 0.1 * mean|Wout|
            __shared__ float sred[4];
            float v = 0.f;
            #pragma unroll
            for (int i = tid; i < OUTC * NF; i += 128) v += fabsf(Wout[i]);
            #pragma unroll
            for (int off = 16; off > 0; off >>= 1)
                v += __shfl_xor_sync(0xffffffffu, v, off);
            if ((tid & 31) == 0) sred[tid >> 5] = v;
            __syncthreads();
            if (tid == 0) {
                float tot = sred[0] + sred[1] + sred[2] + sred[3];
                d_out[OFF_LOSS] = 0.1f * tot / (float)(OUTC * NF);
            }
        }

        __syncthreads();
        if (tid == 0) {
            int v = atomicAdd(&g_ctr2, 1);
            if (v == NHEAD - 1) {
                // last head block resets counters for the next graph replay
                atomicExch(&g_ctr, 0);
                atomicExch(&g_ctr2, 0);
            }
        }
    }
}

// ---------------------------------------------------------------------------
extern "C" void kernel_launch(void* const* d_in, const int* in_sizes, int n_in,
                              void* d_out, int out_size) {
    const float* x    = (const float*)d_in[0];
    const float* w0   = (const float*)d_in[1];
    const float* w1   = (const float*)d_in[2];
    const float* w2   = (const float*)d_in[3];
    const float* w3   = (const float*)d_in[4];
    const float* Wout = (const float*)d_in[5];
    float* out = (float*)d_out;

    fused_kernel<<<NWORKBLK + NHEAD, 128>>>(x, w0, w1, w2, w3, Wout, out);
}

// round 11
// speedup vs baseline: 1.8533x; 1.0917x over previous
#include <cuda_runtime.h>
#include <math_constants.h>

#define B    32
#define T    336
#define C    7
#define NSH  5
#define NG   4
#define NF   140            // 4 groups * 5 * 7
#define OUTC 10
#define NWORKBLK (B * C * NSH)      // 1120 worker blocks (bc, nn); 4 warps = 4 g's
#define NWARPS   (B * C * NG * NSH) // 4480 warp work items
#define NHEAD    21                 // 20 dot blocks + 1 loss block

// offsets in d_out (floats): out[320] | dists[4480] | probs[4480] | loss[1]
#define OFF_OUT   0
#define OFF_DIST  320
#define OFF_PROB  (320 + B*NF)
#define OFF_LOSS  (320 + 2*B*NF)

#define SXN 352            // padded row length (floats, 8B-multiple, zero tail)

__device__ int g_ctr  = 0;   // worker warps completed
__device__ int g_ctr2 = 0;   // head blocks completed

// ---------------------------------------------------------------------------
// One warp: min over all windows of one (bc, g, nn).
// Pair base bb = 2*beta, beta = min(ll + 32*m, BETAMAX). Natural-order row in
// smem; every (x[2i],x[2i+1]) needed is an aligned float2 -> 1 LDS.64 feeds
// 2 windows x 2 l-steps (8 FADD). w consumed as broadcast float2.
// Pairs whose second window is out of range accumulate from +inf.
// ---------------------------------------------------------------------------
template<int L, int M>
__device__ __forceinline__ float warp_sliding_v2(const float* __restrict__ sx,
                                                 const float* __restrict__ swg,
                                                 int ll) {
    constexpr int TW      = T - L + 1;
    constexpr int BETAMAX = (TW - 1) / 2;
    constexpr int H       = L / 2;

    const float2* sx2 = reinterpret_cast<const float2*>(sx);
    const float2* sw2 = reinterpret_cast<const float2*>(swg);

    int    beta[M];
    float  a0[M], a1[M];
    float2 cur[M];
    #pragma unroll
    for (int m = 0; m < M; m++) {
        int bt = ll + 32 * m;
        if (bt > BETAMAX) bt = BETAMAX;            // duplicate work, min-safe
        beta[m] = bt;
        a0[m] = 0.f;
        a1[m] = (2 * bt + 1 < TW) ? 0.f : CUDART_INF_F;
        cur[m] = sx2[bt];                           // (x[bb], x[bb+1])
    }

    #pragma unroll 2
    for (int h = 0; h < H; h++) {
        const float2 w = sw2[h];                    // broadcast LDS.64
        #pragma unroll
        for (int m = 0; m < M; m++) {
            const float2 nxt = sx2[beta[m] + h + 1]; // 1 LDS.64, stride-1 lanes
            // l = 2h   : a0 uses x[bb+2h]   = cur.x ; a1 uses x[bb+2h+1] = cur.y
            a0[m] += fabsf(cur[m].x - w.x);
            a1[m] += fabsf(cur[m].y - w.x);
            // l = 2h+1 : a0 uses x[bb+2h+1] = cur.y ; a1 uses x[bb+2h+2] = nxt.x
            a0[m] += fabsf(cur[m].y - w.y);
            a1[m] += fabsf(nxt.x    - w.y);
            cur[m] = nxt;
        }
    }
    if (L & 1) {                                    // final step l = L-1
        const float w = swg[L - 1];
        #pragma unroll
        for (int m = 0; m < M; m++) {
            a0[m] += fabsf(cur[m].x - w);
            a1[m] += fabsf(cur[m].y - w);
        }
    }

    float mn = CUDART_INF_F;
    #pragma unroll
    for (int m = 0; m < M; m++) mn = fminf(mn, fminf(a0[m], a1[m]));
    #pragma unroll
    for (int o = 16; o > 0; o >>= 1)
        mn = fminf(mn, __shfl_xor_sync(0xffffffffu, mn, o));
    return mn * (1.0f / (float)L);
}

// sw row offsets (even, 8B-aligned): g0@0(34) g1@36(68) g2@104(101) g3@208(168)
#define SW_TOT 376

// ---------------------------------------------------------------------------
// Single launch. grid.x = 1120 workers + 21 head blocks, 128 threads.
// ---------------------------------------------------------------------------
__global__ __launch_bounds__(128, 8) void fused_kernel(
        const float* __restrict__ x,
        const float* __restrict__ w0,
        const float* __restrict__ w1,
        const float* __restrict__ w2,
        const float* __restrict__ w3,
        const float* __restrict__ Wout,
        float* __restrict__ d_out) {
    const int bid = blockIdx.x;
    const int tid = threadIdx.x;          // 128

    if (bid < NWORKBLK) {
        // ================= WORKER =================
        const int nn = bid % NSH;
        const int bc = bid / NSH;
        const int b  = bc / C;
        const int ch = bc % C;
        const int wp = tid >> 5;             // warp 0..3
        const int ll = tid & 31;
        const int g  = (wp + bid) & 3;       // rotate g across blocks/SMSPs

        __shared__ __align__(16) float sx[SXN];
        __shared__ __align__(16) float sw[SW_TOT];
        __shared__ float red[8];

        // ---- normalization: one pass sum + sumsq over the (b,ch) row ----
        const float* xrow = x + (size_t)b * T * C + ch;   // stride C over t
        float vals[3];
        float s = 0.f, ss = 0.f;
        #pragma unroll
        for (int i = 0; i < 3; i++) {
            int t = tid + i * 128;
            float v = (t < T) ? xrow[(size_t)t * C] : 0.f;
            vals[i] = v;
            s += v;
            ss += v * v;
        }
        #pragma unroll
        for (int o = 16; o > 0; o >>= 1) {
            s  += __shfl_xor_sync(0xffffffffu, s, o);
            ss += __shfl_xor_sync(0xffffffffu, ss, o);
        }
        if (ll == 0) { red[wp] = s; red[4 + wp] = ss; }

        // ---- each warp loads its own shapelet row meanwhile ----
        int L, goff;
        const float* wg;
        switch (g) {
            case 0:  L = 34;  goff = 0;   wg = w0; break;
            case 1:  L = 68;  goff = 36;  wg = w1; break;
            case 2:  L = 101; goff = 104; wg = w2; break;
            default: L = 168; goff = 208; wg = w3; break;
        }
        const float* wrow = wg + (size_t)(nn * C + ch) * L;
        for (int i = ll; i < L; i += 32) sw[goff + i] = wrow[i];

        __syncthreads();
        const float stot  = red[0] + red[1] + red[2] + red[3];
        const float sstot = red[4] + red[5] + red[6] + red[7];
        const float mu  = stot * (1.0f / (float)T);
        const float var = (sstot - (float)T * mu * mu) * (1.0f / (float)(T - 1));
        const float inv = 1.0f / (sqrtf(fmaxf(var, 0.f)) + 1e-8f);

        #pragma unroll
        for (int i = 0; i < 3; i++) {
            int t = tid + i * 128;
            if (t < T) sx[t] = (vals[i] - mu) * inv;
        }
        if (tid < SXN - T) sx[T + tid] = 0.f;   // zero pad (only +inf pairs read it)
        __syncthreads();

        // ---- per-warp sliding min (float2, conflict-free) ----
        float dmin;
        switch (g) {
            case 0:  dmin = warp_sliding_v2<34, 5>(sx, sw + 0,   ll); break;
            case 1:  dmin = warp_sliding_v2<68, 5>(sx, sw + 36,  ll); break;
            case 2:  dmin = warp_sliding_v2<101,4>(sx, sw + 104, ll); break;
            default: dmin = warp_sliding_v2<168,3>(sx, sw + 208, ll); break;
        }

        if (ll == 0) {
            const int idx = b * NF + g * (NSH * C) + nn * C + ch;
            d_out[OFF_DIST + idx] = dmin;
            d_out[OFF_PROB + idx] = expf(-dmin * dmin);   // EPS_GATE = 1
            __threadfence();
            atomicAdd(&g_ctr, 1);        // publish this warp's result
        }
    } else {
        // ================= HEAD =================
        const int h = bid - NWORKBLK;    // 0..20

        if (tid == 0) {
            while (atomicAdd(&g_ctr, 0) < NWARPS) __nanosleep(64);
        }
        __syncthreads();
        __threadfence();                  // acquire published probs

        if (h < 20) {
            // 16 dots per block; warp wp does 4 dots
            const int wp = tid >> 5;
            const int ln = tid & 31;
            const float* probs = d_out + OFF_PROB;
            #pragma unroll
            for (int d = 0; d < 4; d++) {
                const int dot = h * 16 + wp * 4 + d;     // < 320
                const int bb = dot / OUTC;
                const int o  = dot % OUTC;
                const float* p  = probs + bb * NF;
                const float* wv = Wout + o * NF;
                float v = 0.f;
                #pragma unroll
                for (int f = ln; f < NF; f += 32) v += p[f] * wv[f];
                #pragma unroll
                for (int off = 16; off > 0; off >>= 1)
                    v += __shfl_xor_sync(0xffffffffu, v, off);
                if (ln == 0) d_out[OFF_OUT + dot] = v;
            }
        } else {
            // loss = 0.1 * mean|Wout|
            __shared__ float sred[4];
            float v = 0.f;
            #pragma unroll
            for (int i = tid; i < OUTC * NF; i += 128) v += fabsf(Wout[i]);
            #pragma unroll
            for (int off = 16; off > 0; off >>= 1)
                v += __shfl_xor_sync(0xffffffffu, v, off);
            if ((tid & 31) == 0) sred[tid >> 5] = v;
            __syncthreads();
            if (tid == 0) {
                float tot = sred[0] + sred[1] + sred[2] + sred[3];
                d_out[OFF_LOSS] = 0.1f * tot / (float)(OUTC * NF);
            }
        }

        __syncthreads();
        if (tid == 0) {
            int v = atomicAdd(&g_ctr2, 1);
            if (v == NHEAD - 1) {
                // last head block resets counters for the next graph replay
                atomicExch(&g_ctr, 0);
                atomicExch(&g_ctr2, 0);
            }
        }
    }
}

// ---------------------------------------------------------------------------
extern "C" void kernel_launch(void* const* d_in, const int* in_sizes, int n_in,
                              void* d_out, int out_size) {
    const float* x    = (const float*)d_in[0];
    const float* w0   = (const float*)d_in[1];
    const float* w1   = (const float*)d_in[2];
    const float* w2   = (const float*)d_in[3];
    const float* w3   = (const float*)d_in[4];
    const float* Wout = (const float*)d_in[5];
    float* out = (float*)d_out;

    fused_kernel<<<NWORKBLK + NHEAD, 128>>>(x, w0, w1, w2, w3, Wout, out);
}